// round 3
// baseline (speedup 1.0000x reference)
#include <cuda_runtime.h>
#include <cstdint>

// ---------------------------------------------------------------------------
// Problem constants
// ---------------------------------------------------------------------------
#define MUL     16
#define DIM     64          // 4*MUL
#define SZ      5           // kernel size
#define NTAP    125
#define B_      2
#define NX      64
#define NY      64
#define NZ      64

// Effective conv weights: [tap][ci][co], tap = a*25 + b*5 + c
__device__ float g_W[NTAP * DIM * DIM];

// ---------------------------------------------------------------------------
// Kernel 1: build effective weights
//   Weff[t][ci][co] = 0.1 * K[t][ci][co]  (+ S[ci][co] at center tap t=62)
// ---------------------------------------------------------------------------
__global__ void build_weights(const float* __restrict__ lw0,
                              const float* __restrict__ lw1,
                              const float* __restrict__ tp)
{
    const int t  = blockIdx.x;            // 0..124
    const int a  = t / 25;
    const int b2 = (t / 5) % 5;
    const int c  = t % 5;

    const float lx = -1.f + 0.5f * (float)a;
    const float ly = -1.f + 0.5f * (float)b2;
    const float lz = -1.f + 0.5f * (float)c;
    const float d  = sqrtf(lx*lx + ly*ly + lz*lz);

    float ux = 0.f, uy = 0.f, uz = 0.f;
    if (d > 0.f) { ux = lx / d; uy = ly / d; uz = lz / d; }
    const float SQ3 = 1.7320508075688772f;
    const float sh1v0 = SQ3 * uy;   // sh1 = sqrt(3)*unit[[1,2,0]]
    const float sh1v1 = SQ3 * uz;
    const float sh1v2 = SQ3 * ux;

    // soft_one_hot * tp_weight, then * cos(pi d)/5^1.5
    const float scale = cosf(3.14159265358979323846f * d) / 11.180339887498949f;
    float coef[5];
#pragma unroll
    for (int s = 0; s < 5; s++) {
        float u = (d - 0.25f * (float)s) / 0.25f;
        coef[s] = expf(-u * u) * (1.0f / 1.12f) * scale;
    }

    float* W = g_W + t * (DIM * DIM);   // [ci][co]

    // zero the whole 64x64 tap slab first (non-covered entries are zero)
    for (int i = threadIdx.x; i < DIM * DIM; i += blockDim.x) W[i] = 0.f;
    __syncthreads();

    // one thread per (u,w) pair; 256 threads exactly
    const int u_ = threadIdx.x >> 4;   // 0..15
    const int w_ = threadIdx.x & 15;   // 0..15
    const int m  = u_ * 16 + w_;

    float eA = 0.f, eB = 0.f, eC = 0.f, eD = 0.f;
#pragma unroll
    for (int s = 0; s < 5; s++) {
        const float cs = coef[s];
        eA += cs * tp[s * 1024 +   0 + m];
        eB += cs * tp[s * 1024 + 256 + m];
        eC += cs * tp[s * 1024 + 512 + m];
        eD += cs * tp[s * 1024 + 768 + m];
    }

    const float A0  = 0.17677669529663689f;   // sqrt(1/32)
    const float A1  = 0.30618621784789724f;   // sqrt(3/32)
    const float IS3 = 0.57735026918962576f;   // 1/sqrt(3)
    const float inv = 0.25f;                  // 1/sqrt(MUL)
    const bool  center = (t == 62);           // (2,2,2)

    // k00: row u, col w
    {
        float v = 0.1f * A0 * eA;
        if (center) v += inv * lw0[u_ * 16 + w_];
        W[u_ * DIM + w_] = v;
    }
    // k01: row u, col 16 + 3w + k
    {
        const float base = 0.1f * A1 * IS3 * eB;
        W[u_ * DIM + 16 + w_ * 3 + 0] = base * sh1v0;
        W[u_ * DIM + 16 + w_ * 3 + 1] = base * sh1v1;
        W[u_ * DIM + 16 + w_ * 3 + 2] = base * sh1v2;
    }
    // k10: row 16 + 3u + i, col w      and k11 diagonal: col 16 + 3w + i
    {
        const float base10 = 0.1f * A0 * IS3 * eD;
        float v11 = 0.1f * A1 * IS3 * eC;
        if (center) v11 += inv * lw1[u_ * 16 + w_];
        const float sh[3] = { sh1v0, sh1v1, sh1v2 };
#pragma unroll
        for (int i = 0; i < 3; i++) {
            W[(16 + u_ * 3 + i) * DIM + w_]                = base10 * sh[i];
            W[(16 + u_ * 3 + i) * DIM + 16 + w_ * 3 + i]   = v11;
        }
    }
}

// ---------------------------------------------------------------------------
// f32x2 helpers (Blackwell packed dual-fp32 FMA; only reachable via PTX)
// ---------------------------------------------------------------------------
__device__ __forceinline__ unsigned long long dup_f32x2(float v) {
    unsigned long long r;
    asm("mov.b64 %0, {%1, %1};" : "=l"(r) : "f"(v));
    return r;
}
__device__ __forceinline__ void ffma2(unsigned long long& d,
                                      unsigned long long a,
                                      unsigned long long b) {
    asm("fma.rn.f32x2 %0, %1, %2, %0;" : "+l"(d) : "l"(a), "l"(b));
}
__device__ __forceinline__ void unpack2(unsigned long long v, float& lo, float& hi) {
    asm("mov.b64 {%0, %1}, %2;" : "=f"(lo), "=f"(hi) : "l"(v));
}

// ---------------------------------------------------------------------------
// Kernel 2: direct conv, block = (b, x0, y0), computes 64 cout x 64 z
//   smem: sIn[64 ci][72]  (z-halo, cols j -> z = j-2)
//         sW [5 c][64 ci][64 co]   (one (a,b) weight slab)
// ---------------------------------------------------------------------------
#define SIN_STRIDE 72
#define SIN_FLOATS (DIM * SIN_STRIDE)            // 4608
#define SW_FLOATS  (SZ * DIM * DIM)              // 20480
#define SMEM_BYTES ((SIN_FLOATS + SW_FLOATS) * 4)  // 100352

__global__ void __launch_bounds__(256, 2)
conv_kernel(const float* __restrict__ x, float* __restrict__ out)
{
    extern __shared__ float smem[];
    float* sIn = smem;                 // [64][72]
    float* sW  = smem + SIN_FLOATS;    // [5][64][64]

    const int gid = blockIdx.x;
    const int y0  = gid & 63;
    const int x0  = (gid >> 6) & 63;
    const int b   = gid >> 12;

    const int t  = threadIdx.x;
    const int zq = t & 15;     // z base = zq*4
    const int cq = t >> 4;     // co base = cq*4

    // acc[p][j]: f32x2 pair = (out[co=4cq+2p][z=4zq+j], out[co=4cq+2p+1][z])
    unsigned long long acc[2][4];
#pragma unroll
    for (int p = 0; p < 2; p++)
#pragma unroll
        for (int j = 0; j < 4; j++) acc[p][j] = 0ULL;

#pragma unroll 1
    for (int a = 0; a < 5; a++) {
        const int xi = x0 + a - 2;
        if ((unsigned)xi >= (unsigned)NX) continue;
#pragma unroll 1
        for (int bb = 0; bb < 5; bb++) {
            const int yi = y0 + bb - 2;
            if ((unsigned)yi >= (unsigned)NY) continue;

            __syncthreads();   // previous iteration's compute done before overwrite

            // load 64 input rows with z halo (cols 0..67; 68..71 unused pad)
            {
                const float* xb = x + ((((size_t)b * DIM) * NX + xi) * NY + yi) * NZ;
                for (int idx = t; idx < DIM * 68; idx += 256) {
                    const int ci = idx / 68;
                    const int j  = idx - ci * 68;
                    const int z  = j - 2;
                    float v = 0.f;
                    if ((unsigned)z < (unsigned)NZ)
                        v = xb[(size_t)ci * (NX * NY * NZ) + z];
                    sIn[ci * SIN_STRIDE + j] = v;
                }
            }
            // load weight slab for (a,bb): 5*64*64 floats, contiguous
            {
                const float4* src4 = (const float4*)(g_W + (size_t)(a * 5 + bb) * SW_FLOATS);
                float4* dst4 = (float4*)sW;
                for (int idx = t; idx < SW_FLOATS / 4; idx += 256)
                    dst4[idx] = src4[idx];
            }
            __syncthreads();

#pragma unroll 2
            for (int ci = 0; ci < DIM; ci++) {
                const float* row = &sIn[ci * SIN_STRIDE + (zq << 2)];
                const float4 f0 = *(const float4*)(row);
                const float4 f1 = *(const float4*)(row + 4);
                const float r[8] = { f0.x, f0.y, f0.z, f0.w,
                                     f1.x, f1.y, f1.z, f1.w };
                unsigned long long dup[8];
#pragma unroll
                for (int k = 0; k < 8; k++) dup[k] = dup_f32x2(r[k]);

#pragma unroll
                for (int c = 0; c < 5; c++) {
                    const ulonglong2 wp =
                        *(const ulonglong2*)&sW[((c * DIM) + ci) * DIM + (cq << 2)];
#pragma unroll
                    for (int j = 0; j < 4; j++) {
                        ffma2(acc[0][j], wp.x, dup[c + j]);
                        ffma2(acc[1][j], wp.y, dup[c + j]);
                    }
                }
            }
        }
    }

    // write: 4 cout x 4 z per thread, float4 along z
    const size_t obase = ((((size_t)b * DIM) * NX + x0) * NY + y0) * NZ + (zq << 2);
#pragma unroll
    for (int p = 0; p < 2; p++) {
        float lo0, hi0, lo1, hi1, lo2, hi2, lo3, hi3;
        unpack2(acc[p][0], lo0, hi0);
        unpack2(acc[p][1], lo1, hi1);
        unpack2(acc[p][2], lo2, hi2);
        unpack2(acc[p][3], lo3, hi3);
        const int co_lo = (cq << 2) + 2 * p;
        float4 vlo = { lo0, lo1, lo2, lo3 };
        float4 vhi = { hi0, hi1, hi2, hi3 };
        *(float4*)(out + obase + (size_t)co_lo       * (NX * NY * NZ)) = vlo;
        *(float4*)(out + obase + (size_t)(co_lo + 1) * (NX * NY * NZ)) = vhi;
    }
}

// ---------------------------------------------------------------------------
// Launch
// ---------------------------------------------------------------------------
extern "C" void kernel_launch(void* const* d_in, const int* in_sizes, int n_in,
                              void* d_out, int out_size)
{
    const float* x   = (const float*)d_in[0];   // (2,64,64,64,64)
    const float* lw0 = (const float*)d_in[1];   // (16,16)
    const float* lw1 = (const float*)d_in[2];   // (16,16)
    const float* tp  = (const float*)d_in[3];   // (5,1024)
    float* out = (float*)d_out;

    build_weights<<<NTAP, 256>>>(lw0, lw1, tp);

    cudaFuncSetAttribute(conv_kernel,
                         cudaFuncAttributeMaxDynamicSharedMemorySize, SMEM_BYTES);
    conv_kernel<<<B_ * NX * NY, 256, SMEM_BYTES>>>(x, out);
}

// round 4
// speedup vs baseline: 1.0018x; 1.0018x over previous
#include <cuda_runtime.h>
#include <cstdint>

// ---------------------------------------------------------------------------
// Problem constants
// ---------------------------------------------------------------------------
#define MUL     16
#define DIM     64          // 4*MUL
#define SZ      5           // kernel size
#define NTAP    125
#define B_      2
#define NX      64
#define NY      64
#define NZ      64

// Effective conv weights: [tap][ci][co], tap = a*25 + b*5 + c
__device__ float g_W[NTAP * DIM * DIM];

// ---------------------------------------------------------------------------
// Kernel 1: build effective weights
//   Weff[t][ci][co] = 0.1 * K[t][ci][co]  (+ S[ci][co] at center tap t=62)
// ---------------------------------------------------------------------------
__global__ void build_weights(const float* __restrict__ lw0,
                              const float* __restrict__ lw1,
                              const float* __restrict__ tp)
{
    const int t  = blockIdx.x;            // 0..124
    const int a  = t / 25;
    const int b2 = (t / 5) % 5;
    const int c  = t % 5;

    const float lx = -1.f + 0.5f * (float)a;
    const float ly = -1.f + 0.5f * (float)b2;
    const float lz = -1.f + 0.5f * (float)c;
    const float d  = sqrtf(lx*lx + ly*ly + lz*lz);

    float ux = 0.f, uy = 0.f, uz = 0.f;
    if (d > 0.f) { ux = lx / d; uy = ly / d; uz = lz / d; }
    const float SQ3 = 1.7320508075688772f;
    const float sh1v0 = SQ3 * uy;   // sh1 = sqrt(3)*unit[[1,2,0]]
    const float sh1v1 = SQ3 * uz;
    const float sh1v2 = SQ3 * ux;

    // soft_one_hot * tp_weight, then * cos(pi d)/5^1.5
    const float scale = cosf(3.14159265358979323846f * d) / 11.180339887498949f;
    float coef[5];
#pragma unroll
    for (int s = 0; s < 5; s++) {
        float u = (d - 0.25f * (float)s) / 0.25f;
        coef[s] = expf(-u * u) * (1.0f / 1.12f) * scale;
    }

    float* W = g_W + t * (DIM * DIM);   // [ci][co]

    // zero the whole 64x64 tap slab first (non-covered entries are zero)
    for (int i = threadIdx.x; i < DIM * DIM; i += blockDim.x) W[i] = 0.f;
    __syncthreads();

    // one thread per (u,w) pair; 256 threads exactly
    const int u_ = threadIdx.x >> 4;   // 0..15
    const int w_ = threadIdx.x & 15;   // 0..15
    const int m  = u_ * 16 + w_;

    float eA = 0.f, eB = 0.f, eC = 0.f, eD = 0.f;
#pragma unroll
    for (int s = 0; s < 5; s++) {
        const float cs = coef[s];
        eA += cs * tp[s * 1024 +   0 + m];
        eB += cs * tp[s * 1024 + 256 + m];
        eC += cs * tp[s * 1024 + 512 + m];
        eD += cs * tp[s * 1024 + 768 + m];
    }

    const float A0  = 0.17677669529663689f;   // sqrt(1/32)
    const float A1  = 0.30618621784789724f;   // sqrt(3/32)
    const float IS3 = 0.57735026918962576f;   // 1/sqrt(3)
    const float inv = 0.25f;                  // 1/sqrt(MUL)
    const bool  center = (t == 62);           // (2,2,2)

    // k00: row u, col w
    {
        float v = 0.1f * A0 * eA;
        if (center) v += inv * lw0[u_ * 16 + w_];
        W[u_ * DIM + w_] = v;
    }
    // k01: row u, col 16 + 3w + k
    {
        const float base = 0.1f * A1 * IS3 * eB;
        W[u_ * DIM + 16 + w_ * 3 + 0] = base * sh1v0;
        W[u_ * DIM + 16 + w_ * 3 + 1] = base * sh1v1;
        W[u_ * DIM + 16 + w_ * 3 + 2] = base * sh1v2;
    }
    // k10: row 16 + 3u + i, col w      and k11 diagonal: col 16 + 3w + i
    {
        const float base10 = 0.1f * A0 * IS3 * eD;
        float v11 = 0.1f * A1 * IS3 * eC;
        if (center) v11 += inv * lw1[u_ * 16 + w_];
        const float sh[3] = { sh1v0, sh1v1, sh1v2 };
#pragma unroll
        for (int i = 0; i < 3; i++) {
            W[(16 + u_ * 3 + i) * DIM + w_]                = base10 * sh[i];
            W[(16 + u_ * 3 + i) * DIM + 16 + w_ * 3 + i]   = v11;
        }
    }
}

// ---------------------------------------------------------------------------
// f32x2 helpers (Blackwell packed dual-fp32 FMA; only reachable via PTX)
// ---------------------------------------------------------------------------
__device__ __forceinline__ unsigned long long dup_f32x2(float v) {
    unsigned long long r;
    asm("mov.b64 %0, {%1, %1};" : "=l"(r) : "f"(v));
    return r;
}
__device__ __forceinline__ void ffma2(unsigned long long& d,
                                      unsigned long long a,
                                      unsigned long long b) {
    asm("fma.rn.f32x2 %0, %1, %2, %0;" : "+l"(d) : "l"(a), "l"(b));
}
__device__ __forceinline__ void unpack2(unsigned long long v, float& lo, float& hi) {
    asm("mov.b64 {%0, %1}, %2;" : "=f"(lo), "=f"(hi) : "l"(v));
}

// ---------------------------------------------------------------------------
// Kernel 2: direct conv, block = (b, x0, y0), computes 64 cout x 64 z
//   smem: sIn[64 ci][72]  (z-halo, cols j -> z = j-2)
//         sW [5 c][64 ci][64 co]   (one (a,b) weight slab)
// ---------------------------------------------------------------------------
#define SIN_STRIDE 72
#define SIN_FLOATS (DIM * SIN_STRIDE)            // 4608
#define SW_FLOATS  (SZ * DIM * DIM)              // 20480
#define SMEM_BYTES ((SIN_FLOATS + SW_FLOATS) * 4)  // 100352

__global__ void __launch_bounds__(256, 2)
conv_kernel(const float* __restrict__ x, float* __restrict__ out)
{
    extern __shared__ float smem[];
    float* sIn = smem;                 // [64][72]
    float* sW  = smem + SIN_FLOATS;    // [5][64][64]

    const int gid = blockIdx.x;
    const int y0  = gid & 63;
    const int x0  = (gid >> 6) & 63;
    const int b   = gid >> 12;

    const int t  = threadIdx.x;
    const int zq = t & 15;     // z base = zq*4
    const int cq = t >> 4;     // co base = cq*4

    // acc[p][j]: f32x2 pair = (out[co=4cq+2p][z=4zq+j], out[co=4cq+2p+1][z])
    unsigned long long acc[2][4];
#pragma unroll
    for (int p = 0; p < 2; p++)
#pragma unroll
        for (int j = 0; j < 4; j++) acc[p][j] = 0ULL;

#pragma unroll 1
    for (int a = 0; a < 5; a++) {
        const int xi = x0 + a - 2;
        if ((unsigned)xi >= (unsigned)NX) continue;
#pragma unroll 1
        for (int bb = 0; bb < 5; bb++) {
            const int yi = y0 + bb - 2;
            if ((unsigned)yi >= (unsigned)NY) continue;

            __syncthreads();   // previous iteration's compute done before overwrite

            // load 64 input rows with z halo (cols 0..67; 68..71 unused pad)
            {
                const float* xb = x + ((((size_t)b * DIM) * NX + xi) * NY + yi) * NZ;
                for (int idx = t; idx < DIM * 68; idx += 256) {
                    const int ci = idx / 68;
                    const int j  = idx - ci * 68;
                    const int z  = j - 2;
                    float v = 0.f;
                    if ((unsigned)z < (unsigned)NZ)
                        v = xb[(size_t)ci * (NX * NY * NZ) + z];
                    sIn[ci * SIN_STRIDE + j] = v;
                }
            }
            // load weight slab for (a,bb): 5*64*64 floats, contiguous
            {
                const float4* src4 = (const float4*)(g_W + (size_t)(a * 5 + bb) * SW_FLOATS);
                float4* dst4 = (float4*)sW;
                for (int idx = t; idx < SW_FLOATS / 4; idx += 256)
                    dst4[idx] = src4[idx];
            }
            __syncthreads();

#pragma unroll 2
            for (int ci = 0; ci < DIM; ci++) {
                const float* row = &sIn[ci * SIN_STRIDE + (zq << 2)];
                const float4 f0 = *(const float4*)(row);
                const float4 f1 = *(const float4*)(row + 4);
                const float r[8] = { f0.x, f0.y, f0.z, f0.w,
                                     f1.x, f1.y, f1.z, f1.w };
                unsigned long long dup[8];
#pragma unroll
                for (int k = 0; k < 8; k++) dup[k] = dup_f32x2(r[k]);

#pragma unroll
                for (int c = 0; c < 5; c++) {
                    const ulonglong2 wp =
                        *(const ulonglong2*)&sW[((c * DIM) + ci) * DIM + (cq << 2)];
#pragma unroll
                    for (int j = 0; j < 4; j++) {
                        ffma2(acc[0][j], wp.x, dup[c + j]);
                        ffma2(acc[1][j], wp.y, dup[c + j]);
                    }
                }
            }
        }
    }

    // write: 4 cout x 4 z per thread, float4 along z
    const size_t obase = ((((size_t)b * DIM) * NX + x0) * NY + y0) * NZ + (zq << 2);
#pragma unroll
    for (int p = 0; p < 2; p++) {
        float lo0, hi0, lo1, hi1, lo2, hi2, lo3, hi3;
        unpack2(acc[p][0], lo0, hi0);
        unpack2(acc[p][1], lo1, hi1);
        unpack2(acc[p][2], lo2, hi2);
        unpack2(acc[p][3], lo3, hi3);
        const int co_lo = (cq << 2) + 2 * p;
        float4 vlo = { lo0, lo1, lo2, lo3 };
        float4 vhi = { hi0, hi1, hi2, hi3 };
        *(float4*)(out + obase + (size_t)co_lo       * (NX * NY * NZ)) = vlo;
        *(float4*)(out + obase + (size_t)(co_lo + 1) * (NX * NY * NZ)) = vhi;
    }
}

// ---------------------------------------------------------------------------
// Launch
// ---------------------------------------------------------------------------
extern "C" void kernel_launch(void* const* d_in, const int* in_sizes, int n_in,
                              void* d_out, int out_size)
{
    const float* x   = (const float*)d_in[0];   // (2,64,64,64,64)
    const float* lw0 = (const float*)d_in[1];   // (16,16)
    const float* lw1 = (const float*)d_in[2];   // (16,16)
    const float* tp  = (const float*)d_in[3];   // (5,1024)
    float* out = (float*)d_out;

    build_weights<<<NTAP, 256>>>(lw0, lw1, tp);

    cudaFuncSetAttribute(conv_kernel,
                         cudaFuncAttributeMaxDynamicSharedMemorySize, SMEM_BYTES);
    conv_kernel<<<B_ * NX * NY, 256, SMEM_BYTES>>>(x, out);
}